// round 2
// baseline (speedup 1.0000x reference)
#include <cuda_runtime.h>
#include <cstdint>

// Problem constants
#define B    8
#define D    256
#define TC   2048
#define TE   2048
#define TGT  256
#define TWOD 512
#define INV_SCALE 0.0625f   // 1/16

// Scratch (allocation-free rule: __device__ globals)
// sim/attn: [B][TC][TE] fp32 = 134 MB
static __device__ float g_sim[33554432];
// weighted^T: [B][D][TC] fp32 = 16.8 MB (stored d-major to feed conv directly)
static __device__ float g_wT[4194304];

// ---------------------------------------------------------------------------
// GEMM1 (TN): sim[b][t][s] = (1/16) * sum_d C[b][d][t] * E[b][d][s]
// A and B are K-outer (k strided, m/n contiguous) -> direct coalesced tiles.
// Tile 64x64x16, 256 threads, 4x4 micro-tile.
// ---------------------------------------------------------------------------
__global__ __launch_bounds__(256) void gemm_qk_kernel(
    const float* __restrict__ content, const float* __restrict__ emotion)
{
    const int b  = blockIdx.z;
    const int t0 = blockIdx.x * 64;
    const int s0 = blockIdx.y * 64;

    const float* A = content + (size_t)b * D * TC;   // [D][TC]
    const float* Bm = emotion + (size_t)b * D * TE;  // [D][TE]

    __shared__ float As[16][64];
    __shared__ float Bs[16][64];

    const int tid = threadIdx.x;
    const int tx = tid & 15;
    const int ty = tid >> 4;
    const int lk = tid >> 4;          // 0..15
    const int lm = (tid & 15) * 4;    // 0..60

    float acc[4][4] = {};

    for (int k0 = 0; k0 < D; k0 += 16) {
        *(float4*)&As[lk][lm] = *(const float4*)&A[(size_t)(k0 + lk) * TC + t0 + lm];
        *(float4*)&Bs[lk][lm] = *(const float4*)&Bm[(size_t)(k0 + lk) * TE + s0 + lm];
        __syncthreads();
#pragma unroll
        for (int kk = 0; kk < 16; kk++) {
            const float4 a = *(const float4*)&As[kk][ty * 4];
            const float4 bb = *(const float4*)&Bs[kk][tx * 4];
            const float ar[4] = {a.x, a.y, a.z, a.w};
            const float br[4] = {bb.x, bb.y, bb.z, bb.w};
#pragma unroll
            for (int i = 0; i < 4; i++)
#pragma unroll
                for (int j = 0; j < 4; j++)
                    acc[i][j] += ar[i] * br[j];
        }
        __syncthreads();
    }

    float* Crow = g_sim + (size_t)b * TC * TE;
#pragma unroll
    for (int i = 0; i < 4; i++) {
        float4 st;
        st.x = acc[i][0] * INV_SCALE;
        st.y = acc[i][1] * INV_SCALE;
        st.z = acc[i][2] * INV_SCALE;
        st.w = acc[i][3] * INV_SCALE;
        *(float4*)&Crow[(size_t)(t0 + ty * 4 + i) * TE + s0 + tx * 4] = st;
    }
}

// ---------------------------------------------------------------------------
// Row softmax over TE=2048, in place. One block per row, 256 threads x 8 elems.
// ---------------------------------------------------------------------------
__global__ __launch_bounds__(256) void softmax_kernel()
{
    const size_t row = blockIdx.x;
    float* p = g_sim + row * TE;
    const int tid = threadIdx.x;

    float v[8];
    float mx = -1e30f;
#pragma unroll
    for (int j = 0; j < 8; j++) {
        v[j] = p[tid + j * 256];
        mx = fmaxf(mx, v[j]);
    }

    __shared__ float red[256];
    red[tid] = mx;
    __syncthreads();
    for (int s = 128; s > 0; s >>= 1) {
        if (tid < s) red[tid] = fmaxf(red[tid], red[tid + s]);
        __syncthreads();
    }
    mx = red[0];
    __syncthreads();

    float sum = 0.f;
#pragma unroll
    for (int j = 0; j < 8; j++) {
        v[j] = __expf(v[j] - mx);
        sum += v[j];
    }
    red[tid] = sum;
    __syncthreads();
    for (int s = 128; s > 0; s >>= 1) {
        if (tid < s) red[tid] += red[tid + s];
        __syncthreads();
    }
    const float inv = 1.0f / red[0];

#pragma unroll
    for (int j = 0; j < 8; j++)
        p[tid + j * 256] = v[j] * inv;
}

// ---------------------------------------------------------------------------
// GEMM2 (NT): wT[b][d][t] = sum_s E[b][d][s] * attn[b][t][s]
// Both operands row-major with K(=s) contiguous -> load with K-contig float4,
// store transposed into padded smem tiles.
// M = d (256), N = t (2048), K = s (2048).
// ---------------------------------------------------------------------------
__global__ __launch_bounds__(256) void gemm_av_kernel(
    const float* __restrict__ emotion)
{
    const int b  = blockIdx.z;
    const int n0 = blockIdx.x * 64;   // t tile
    const int m0 = blockIdx.y * 64;   // d tile

    const float* A = emotion + (size_t)b * D * TE;     // [D][TE]  (M x K)
    const float* Bm = g_sim  + (size_t)b * TC * TE;    // [TC][TE] (N x K)

    __shared__ float As[16][68];
    __shared__ float Bs[16][68];

    const int tid = threadIdx.x;
    const int tx = tid & 15;
    const int ty = tid >> 4;
    const int lr = tid >> 2;          // 0..63 : m (or n) within tile
    const int lq = (tid & 3) * 4;     // 0,4,8,12 : k offset

    float acc[4][4] = {};

    for (int k0 = 0; k0 < TE; k0 += 16) {
        const float4 a = *(const float4*)&A[(size_t)(m0 + lr) * TE + k0 + lq];
        const float4 bb = *(const float4*)&Bm[(size_t)(n0 + lr) * TE + k0 + lq];
        As[lq + 0][lr] = a.x;  As[lq + 1][lr] = a.y;
        As[lq + 2][lr] = a.z;  As[lq + 3][lr] = a.w;
        Bs[lq + 0][lr] = bb.x; Bs[lq + 1][lr] = bb.y;
        Bs[lq + 2][lr] = bb.z; Bs[lq + 3][lr] = bb.w;
        __syncthreads();
#pragma unroll
        for (int kk = 0; kk < 16; kk++) {
            const float4 a4 = *(const float4*)&As[kk][ty * 4];
            const float4 b4 = *(const float4*)&Bs[kk][tx * 4];
            const float ar[4] = {a4.x, a4.y, a4.z, a4.w};
            const float br[4] = {b4.x, b4.y, b4.z, b4.w};
#pragma unroll
            for (int i = 0; i < 4; i++)
#pragma unroll
                for (int j = 0; j < 4; j++)
                    acc[i][j] += ar[i] * br[j];
        }
        __syncthreads();
    }

    float* Wout = g_wT + (size_t)b * D * TC;
#pragma unroll
    for (int i = 0; i < 4; i++) {
        float4 st;
        st.x = acc[i][0]; st.y = acc[i][1]; st.z = acc[i][2]; st.w = acc[i][3];
        *(float4*)&Wout[(size_t)(m0 + ty * 4 + i) * TC + n0 + tx * 4] = st;
    }
}

// ---------------------------------------------------------------------------
// Conv1d k=3, 512 -> 256 channels, pad 1, as a shifted GEMM.
// out[b][o][t] = bias[o] + sum_{i<512} sum_{tap<3} W[o][i][tap] * X[b][i][t+tap-1]
// X[b][i<256][t]  = content[b][i][t]
// X[b][256+i][t]  = g_wT[b][i][t]
// Tile: 64 o x 64 t, 16-channel chunks; haloed X tile (66 cols).
// ---------------------------------------------------------------------------
__global__ __launch_bounds__(256) void conv_kernel(
    const float* __restrict__ content, const float* __restrict__ w,
    const float* __restrict__ bias, float* __restrict__ out)
{
    const int b  = blockIdx.z;
    const int t0 = blockIdx.x * 64;
    const int o0 = blockIdx.y * 64;

    __shared__ float Xs[16][66];
    __shared__ float Ws[64][16][3];

    const int tid = threadIdx.x;
    const int tx = tid & 15;
    const int ty = tid >> 4;

    const float* cbase = content + (size_t)b * D * TC;
    const float* wbase = g_wT    + (size_t)b * D * TC;

    float acc[4][4] = {};

    for (int c0 = 0; c0 < TWOD; c0 += 16) {
        // Load X tile: 16 channels x 66 t (halo of 1 each side), zero padded.
        for (int idx = tid; idx < 16 * 66; idx += 256) {
            const int r   = idx / 66;
            const int col = idx - r * 66;
            const int c   = c0 + r;
            const int tt  = t0 - 1 + col;
            float val = 0.f;
            if (tt >= 0 && tt < TC) {
                const float* src = (c < D) ? (cbase + (size_t)c * TC)
                                           : (wbase + (size_t)(c - D) * TC);
                val = src[tt];
            }
            Xs[r][col] = val;
        }
        // Load W tile: 64 o x 16 i x 3 taps.
        for (int idx = tid; idx < 64 * 16 * 3; idx += 256) {
            const int o   = idx / 48;
            const int rem = idx - o * 48;
            const int ii  = rem / 3;
            const int tap = rem - ii * 3;
            Ws[o][ii][tap] = w[((size_t)(o0 + o) * TWOD + c0 + ii) * 3 + tap];
        }
        __syncthreads();

#pragma unroll
        for (int kk = 0; kk < 16; kk++) {
            float x[6];
#pragma unroll
            for (int j6 = 0; j6 < 6; j6++) x[j6] = Xs[kk][tx * 4 + j6];
#pragma unroll
            for (int i = 0; i < 4; i++) {
                const float w0 = Ws[ty * 4 + i][kk][0];
                const float w1 = Ws[ty * 4 + i][kk][1];
                const float w2 = Ws[ty * 4 + i][kk][2];
#pragma unroll
                for (int j = 0; j < 4; j++)
                    acc[i][j] += w0 * x[j] + w1 * x[j + 1] + w2 * x[j + 2];
            }
        }
        __syncthreads();
    }

    float* obase = out + (size_t)b * TGT * TC;
#pragma unroll
    for (int i = 0; i < 4; i++) {
        const int o = o0 + ty * 4 + i;
        const float bs = bias[o];
        float4 st;
        st.x = acc[i][0] + bs; st.y = acc[i][1] + bs;
        st.z = acc[i][2] + bs; st.w = acc[i][3] + bs;
        *(float4*)&obase[(size_t)o * TC + t0 + tx * 4] = st;
    }
}

// ---------------------------------------------------------------------------
extern "C" void kernel_launch(void* const* d_in, const int* in_sizes, int n_in,
                              void* d_out, int out_size)
{
    const float* content = (const float*)d_in[0];  // [B][D][TC]
    const float* emotion = (const float*)d_in[1];  // [B][D][TE]
    const float* conv_w  = (const float*)d_in[2];  // [TGT][2D][3]
    const float* conv_b  = (const float*)d_in[3];  // [TGT]
    float* out = (float*)d_out;                    // [B][TGT][TC]

    (void)in_sizes; (void)n_in; (void)out_size;

    {   // sim = (C^T E) / 16
        dim3 grid(TC / 64, TE / 64, B);
        gemm_qk_kernel<<<grid, 256>>>(content, emotion);
    }
    {   // softmax rows
        softmax_kernel<<<B * TC, 256>>>();
    }
    {   // weighted^T = E * attn^T
        dim3 grid(TC / 64, D / 64, B);
        gemm_av_kernel<<<grid, 256>>>(emotion);
    }
    {   // conv1d + bias
        dim3 grid(TC / 64, TGT / 64, B);
        conv_kernel<<<grid, 256>>>(content, conv_w, conv_b, out);
    }
}

// round 5
// speedup vs baseline: 2.3507x; 2.3507x over previous
#include <cuda_runtime.h>
#include <cstdint>

// Problem constants
#define B    8
#define D    256
#define TC   2048
#define TE   2048
#define TGT  256
#define K3   1536            // 512 channels * 3 taps (im2col K)
#define INV_SCALE 0.0625f    // 1/16

#define SST 20               // smem row stride in floats (16 data + 4 pad, 80B)

// ---------------------------------------------------------------------------
// Scratch (allocation-free rule: __device__ globals)
// ---------------------------------------------------------------------------
static __device__ float g_sim[(size_t)B * TC * TE];   // 134 MB logits/attn
static __device__ float g_wT[(size_t)B * D * TC];     // 16.8 MB weighted^T
static __device__ float g_x2[(size_t)B * TC * K3];    // 100 MB im2col

// ---------------------------------------------------------------------------
// Helpers
// ---------------------------------------------------------------------------
__device__ __forceinline__ uint32_t to_tf32(float x) {
    uint32_t r;
    asm("cvt.rna.tf32.f32 %0, %1;" : "=r"(r) : "f"(x));
    return r;
}

__device__ __forceinline__ void mma8(float c[4], const uint32_t a[4],
                                     uint32_t b0, uint32_t b1) {
    asm volatile(
        "mma.sync.aligned.m16n8k8.row.col.f32.tf32.tf32.f32 "
        "{%0,%1,%2,%3}, {%4,%5,%6,%7}, {%8,%9}, {%0,%1,%2,%3};"
        : "+f"(c[0]), "+f"(c[1]), "+f"(c[2]), "+f"(c[3])
        : "r"(a[0]), "r"(a[1]), "r"(a[2]), "r"(a[3]), "r"(b0), "r"(b1));
}

// ---------------------------------------------------------------------------
// Staging: tiles are [128 rows][16 k] fp32 (tf32-rounded), row stride SST.
// ---------------------------------------------------------------------------

// Operand K-major in global ([row][k], k contiguous): float4 path.
__device__ __forceinline__ void ldg_km(const float* g, int stride, int k0,
                                       int tid, float4 r[2]) {
#pragma unroll
    for (int it = 0; it < 2; it++) {
        const int idx = it * 256 + tid;          // 0..511
        const int k4 = idx & 3, row = idx >> 2;  // k4*4, row 0..127
        r[it] = *(const float4*)(g + (size_t)row * stride + k0 + k4 * 4);
    }
}
__device__ __forceinline__ void sts_km(uint32_t* S, int tid, const float4 r[2]) {
#pragma unroll
    for (int it = 0; it < 2; it++) {
        const int idx = it * 256 + tid;
        const int k4 = idx & 3, row = idx >> 2;
        uint4 v;
        v.x = to_tf32(r[it].x); v.y = to_tf32(r[it].y);
        v.z = to_tf32(r[it].z); v.w = to_tf32(r[it].w);
        *(uint4*)(S + row * SST + k4 * 4) = v;   // 16B aligned (SST*4=80B rows)
    }
}

// Operand MN-major in global ([k][row], row contiguous): transpose staging.
__device__ __forceinline__ void ldg_tr(const float* g, int stride, int k0,
                                       int tid, float r[8]) {
#pragma unroll
    for (int it = 0; it < 8; it++) {
        const int idx = it * 256 + tid;          // 0..2047
        const int k = idx >> 7, m = idx & 127;
        r[it] = g[(size_t)(k0 + k) * stride + m];
    }
}
__device__ __forceinline__ void sts_tr(uint32_t* S, int tid, const float r[8]) {
#pragma unroll
    for (int it = 0; it < 8; it++) {
        const int idx = it * 256 + tid;
        const int k = idx >> 7, m = idx & 127;
        S[m * SST + k] = to_tf32(r[it]);
    }
}

// ---------------------------------------------------------------------------
// Core warp-tile compute: one K=16 smem tile -> 32 HMMAs per warp.
// Warp tile 64(m) x 32(n); acc[mt][nt][4].
// ---------------------------------------------------------------------------
__device__ __forceinline__ void compute_tile(const uint32_t* As, const uint32_t* Bs,
                                             int arow0, int bcol0, int gr, int tg,
                                             float acc[4][4][4]) {
#pragma unroll
    for (int ks = 0; ks < 16; ks += 8) {
        uint32_t a[4][4];
#pragma unroll
        for (int mt = 0; mt < 4; mt++) {
            const uint32_t* pa = As + (arow0 + mt * 16 + gr) * SST + ks + tg;
            a[mt][0] = pa[0];
            a[mt][2] = pa[4];
            a[mt][1] = pa[8 * SST];
            a[mt][3] = pa[8 * SST + 4];
        }
#pragma unroll
        for (int nt = 0; nt < 4; nt++) {
            const uint32_t* pb = Bs + (bcol0 + nt * 8 + gr) * SST + ks + tg;
            const uint32_t b0 = pb[0], b1 = pb[4];
#pragma unroll
            for (int mt = 0; mt < 4; mt++)
                mma8(acc[mt][nt], a[mt], b0, b1);
        }
    }
}

// ---------------------------------------------------------------------------
// GEMM1: sim[b][t][s] = (1/16) * sum_d C[b][d][t]*E[b][d][s]
// M=t (128-tile), N=s (128-tile), K=D=256. Both operands MN-major -> transpose.
// ---------------------------------------------------------------------------
__global__ __launch_bounds__(256)
void gemm_qk(const float* __restrict__ content, const float* __restrict__ emotion)
{
    __shared__ uint32_t As[128 * SST];
    __shared__ uint32_t Bs[128 * SST];

    const int b = blockIdx.z, t0 = blockIdx.x * 128, s0 = blockIdx.y * 128;
    const float* Ag = content + (size_t)b * D * TC + t0;  // element (m,k) at k*TC+m
    const float* Bg = emotion + (size_t)b * D * TE + s0;

    const int tid = threadIdx.x, wid = tid >> 5, lane = tid & 31;
    const int wm = wid >> 2, wn = wid & 3;
    const int gr = lane >> 2, tg = lane & 3;
    const int arow0 = wm * 64, bcol0 = wn * 32;

    float acc[4][4][4] = {};
    float ra[8], rb[8];
    ldg_tr(Ag, TC, 0, tid, ra);
    ldg_tr(Bg, TE, 0, tid, rb);

    const int NT = D / 16;  // 16
    for (int kt = 0; kt < NT; kt++) {
        sts_tr(As, tid, ra);
        sts_tr(Bs, tid, rb);
        __syncthreads();
        if (kt + 1 < NT) {
            ldg_tr(Ag, TC, (kt + 1) * 16, tid, ra);
            ldg_tr(Bg, TE, (kt + 1) * 16, tid, rb);
        }
        compute_tile(As, Bs, arow0, bcol0, gr, tg, acc);
        __syncthreads();
    }

    float* dst = g_sim + ((size_t)b * TC) * TE;
#pragma unroll
    for (int mt = 0; mt < 4; mt++) {
        const int r0 = t0 + arow0 + mt * 16 + gr;
#pragma unroll
        for (int nt = 0; nt < 4; nt++) {
            const int c = s0 + bcol0 + nt * 8 + tg * 2;
            float2 v0 = { acc[mt][nt][0] * INV_SCALE, acc[mt][nt][1] * INV_SCALE };
            float2 v1 = { acc[mt][nt][2] * INV_SCALE, acc[mt][nt][3] * INV_SCALE };
            *(float2*)(dst + (size_t)r0 * TE + c) = v0;
            *(float2*)(dst + (size_t)(r0 + 8) * TE + c) = v1;
        }
    }
}

// ---------------------------------------------------------------------------
// Row softmax over TE=2048, in place.
// ---------------------------------------------------------------------------
__global__ __launch_bounds__(256) void softmax_kernel()
{
    const size_t row = blockIdx.x;
    float* p = g_sim + row * TE;
    const int tid = threadIdx.x;

    float v[8];
    float mx = -1e30f;
#pragma unroll
    for (int j = 0; j < 8; j++) {
        v[j] = p[tid + j * 256];
        mx = fmaxf(mx, v[j]);
    }
    __shared__ float red[256];
    red[tid] = mx;
    __syncthreads();
    for (int s = 128; s > 0; s >>= 1) {
        if (tid < s) red[tid] = fmaxf(red[tid], red[tid + s]);
        __syncthreads();
    }
    mx = red[0];
    __syncthreads();

    float sum = 0.f;
#pragma unroll
    for (int j = 0; j < 8; j++) { v[j] = __expf(v[j] - mx); sum += v[j]; }
    red[tid] = sum;
    __syncthreads();
    for (int s = 128; s > 0; s >>= 1) {
        if (tid < s) red[tid] += red[tid + s];
        __syncthreads();
    }
    const float inv = 1.0f / red[0];
#pragma unroll
    for (int j = 0; j < 8; j++) p[tid + j * 256] = v[j] * inv;
}

// ---------------------------------------------------------------------------
// GEMM2: wT[b][d][t] = sum_s E[b][d][s]*attn[b][t][s]
// M=d (2 tiles), N=t (16 tiles), K=TE=2048. Both K-major.
// ---------------------------------------------------------------------------
__global__ __launch_bounds__(256)
void gemm_av(const float* __restrict__ emotion)
{
    __shared__ uint32_t As[128 * SST];
    __shared__ uint32_t Bs[128 * SST];

    const int b = blockIdx.z, n0 = blockIdx.x * 128, m0 = blockIdx.y * 128;
    const float* Ag = emotion + (size_t)b * D * TE + (size_t)m0 * TE;
    const float* Bg = g_sim + (size_t)b * TC * TE + (size_t)n0 * TE;

    const int tid = threadIdx.x, wid = tid >> 5, lane = tid & 31;
    const int wm = wid >> 2, wn = wid & 3;
    const int gr = lane >> 2, tg = lane & 3;
    const int arow0 = wm * 64, bcol0 = wn * 32;

    float acc[4][4][4] = {};
    float4 ra[2], rb[2];
    ldg_km(Ag, TE, 0, tid, ra);
    ldg_km(Bg, TE, 0, tid, rb);

    const int NT = TE / 16;  // 128
    for (int kt = 0; kt < NT; kt++) {
        sts_km(As, tid, ra);
        sts_km(Bs, tid, rb);
        __syncthreads();
        if (kt + 1 < NT) {
            ldg_km(Ag, TE, (kt + 1) * 16, tid, ra);
            ldg_km(Bg, TE, (kt + 1) * 16, tid, rb);
        }
        compute_tile(As, Bs, arow0, bcol0, gr, tg, acc);
        __syncthreads();
    }

    float* dst = g_wT + ((size_t)b * D) * TC;
#pragma unroll
    for (int mt = 0; mt < 4; mt++) {
        const int r0 = m0 + arow0 + mt * 16 + gr;   // d
#pragma unroll
        for (int nt = 0; nt < 4; nt++) {
            const int c = n0 + bcol0 + nt * 8 + tg * 2;  // t
            float2 v0 = { acc[mt][nt][0], acc[mt][nt][1] };
            float2 v1 = { acc[mt][nt][2], acc[mt][nt][3] };
            *(float2*)(dst + (size_t)r0 * TC + c) = v0;
            *(float2*)(dst + (size_t)(r0 + 8) * TC + c) = v1;
        }
    }
}

// ---------------------------------------------------------------------------
// im2col: X2[b][t][c*3+tap] = X[b][c][t+tap-1], X = concat(content, wT)
// ---------------------------------------------------------------------------
__global__ __launch_bounds__(256) void im2col_kernel(const float* __restrict__ content)
{
    __shared__ float S[32][132];
    const int b = blockIdx.z, t0 = blockIdx.x * 128, c0 = blockIdx.y * 32;
    const int tid = threadIdx.x;

    for (int idx = tid; idx < 32 * 130; idx += 256) {
        const int c = idx / 130, col = idx - c * 130;
        const int tt = t0 - 1 + col;
        const int cc = c0 + c;
        float v = 0.f;
        if (tt >= 0 && tt < TC)
            v = (cc < D) ? content[((size_t)b * D + cc) * TC + tt]
                         : g_wT[((size_t)b * D + (cc - D)) * TC + tt];
        S[c][col] = v;
    }
    __syncthreads();

    float* dst = g_x2 + ((size_t)b * TC + t0) * K3 + c0 * 3;
    for (int idx = tid; idx < 128 * 96; idx += 256) {
        const int t = idx / 96, kl = idx - t * 96;
        const int c = kl / 3, tap = kl - c * 3;
        dst[(size_t)t * K3 + kl] = S[c][t + tap];
    }
}

// ---------------------------------------------------------------------------
// Conv as GEMM: out[b][o][t] = bias[o] + sum_k3 W[o][k3]*X2[b][t][k3]
// M=o (2 tiles), N=t (16 tiles), K=1536. Both K-major.
// ---------------------------------------------------------------------------
__global__ __launch_bounds__(256)
void conv_mm(const float* __restrict__ w, const float* __restrict__ bias,
             float* __restrict__ out)
{
    __shared__ uint32_t As[128 * SST];
    __shared__ uint32_t Bs[128 * SST];

    const int b = blockIdx.z, n0 = blockIdx.x * 128, m0 = blockIdx.y * 128;
    const float* Ag = w + (size_t)m0 * K3;
    const float* Bg = g_x2 + ((size_t)b * TC + n0) * K3;

    const int tid = threadIdx.x, wid = tid >> 5, lane = tid & 31;
    const int wm = wid >> 2, wn = wid & 3;
    const int gr = lane >> 2, tg = lane & 3;
    const int arow0 = wm * 64, bcol0 = wn * 32;

    float acc[4][4][4] = {};
    float4 ra[2], rb[2];
    ldg_km(Ag, K3, 0, tid, ra);
    ldg_km(Bg, K3, 0, tid, rb);

    const int NT = K3 / 16;  // 96
    for (int kt = 0; kt < NT; kt++) {
        sts_km(As, tid, ra);
        sts_km(Bs, tid, rb);
        __syncthreads();
        if (kt + 1 < NT) {
            ldg_km(Ag, K3, (kt + 1) * 16, tid, ra);
            ldg_km(Bg, K3, (kt + 1) * 16, tid, rb);
        }
        compute_tile(As, Bs, arow0, bcol0, gr, tg, acc);
        __syncthreads();
    }

    float* dst = out + ((size_t)b * TGT) * TC;
#pragma unroll
    for (int mt = 0; mt < 4; mt++) {
        const int r0 = m0 + arow0 + mt * 16 + gr;   // o
        const float bs0 = bias[r0], bs1 = bias[r0 + 8];
#pragma unroll
        for (int nt = 0; nt < 4; nt++) {
            const int c = n0 + bcol0 + nt * 8 + tg * 2;  // t
            float2 v0 = { acc[mt][nt][0] + bs0, acc[mt][nt][1] + bs0 };
            float2 v1 = { acc[mt][nt][2] + bs1, acc[mt][nt][3] + bs1 };
            *(float2*)(dst + (size_t)r0 * TC + c) = v0;
            *(float2*)(dst + (size_t)(r0 + 8) * TC + c) = v1;
        }
    }
}

// ---------------------------------------------------------------------------
extern "C" void kernel_launch(void* const* d_in, const int* in_sizes, int n_in,
                              void* d_out, int out_size)
{
    const float* content = (const float*)d_in[0];  // [B][D][TC]
    const float* emotion = (const float*)d_in[1];  // [B][D][TE]
    const float* conv_w  = (const float*)d_in[2];  // [TGT][2D][3] = [TGT][1536]
    const float* conv_b  = (const float*)d_in[3];  // [TGT]
    float* out = (float*)d_out;                    // [B][TGT][TC]
    (void)in_sizes; (void)n_in; (void)out_size;

    gemm_qk<<<dim3(TC / 128, TE / 128, B), 256>>>(content, emotion);
    softmax_kernel<<<B * TC, 256>>>();
    gemm_av<<<dim3(TC / 128, D / 128, B), 256>>>(emotion);
    im2col_kernel<<<dim3(TC / 128, 512 / 32, B), 256>>>(content);
    conv_mm<<<dim3(TC / 128, TGT / 128, B), 256>>>(conv_w, conv_b, out);
}